// round 2
// baseline (speedup 1.0000x reference)
#include <cuda_runtime.h>

#define N_ROWS 65536
#define EDIM 512
#define NE 1024
#define VQ_DEPTH 6
#define CAND_CAP 32

// Scratch (static __device__ globals: allocation-free per harness rules)
__device__ float g_zf[(size_t)N_ROWS * EDIM];   // 128 MB  unfolded input
__device__ float g_u[(size_t)N_ROWS * NE];      // 256 MB  u_j = 2 * r . e_j (depth-0)
__device__ float g_G2[NE * NE];                 // 4 MB    2 * E E^T (approx only)
__device__ float g_esq[NE];
__device__ float g_partial[N_ROWS];

// ---------------------------------------------------------------------------
// unfold: zf[n][d] = x[b][c][2hb+ki][2wb+kj]; block=(b,c,hb), thread=wb.
// Coalesced float2 reads, float4 writes (d = c*4 + ki*2 + kj contiguous).
// ---------------------------------------------------------------------------
__global__ void unfold_kernel(const float* __restrict__ x) {
    int bid = blockIdx.x;
    int b = bid >> 14, c = (bid >> 7) & 127, hb = bid & 127;
    int wb = threadIdx.x;
    const float* xr = x + (((long)((b << 7) + c)) << 16) + ((long)(hb << 1) << 8);
    float2 r0 = *(const float2*)(xr + wb * 2);
    float2 r1 = *(const float2*)(xr + 256 + wb * 2);
    long n = ((long)((b << 7) + hb) << 7) + wb;
    float4 v; v.x = r0.x; v.y = r0.y; v.z = r1.x; v.w = r1.y;
    *(float4*)(g_zf + n * EDIM + c * 4) = v;
}

// ---------------------------------------------------------------------------
// e_sq (exact order irrelevant — uniform-shift argument makes rsq/esq ulp
// discrepancies vs XLA harmless; just needs consistency within this kernel).
// ---------------------------------------------------------------------------
__global__ void esq_kernel(const float* __restrict__ emb) {
    int w = (blockIdx.x * blockDim.x + threadIdx.x) >> 5;  // row 0..1023
    int lane = threadIdx.x & 31;
    const float* e = emb + w * EDIM;
    float acc = 0.f;
    for (int i = lane; i < EDIM; i += 32)
        acc = __fadd_rn(acc, __fmul_rn(e[i], e[i]));
    for (int off = 16; off; off >>= 1)
        acc = __fadd_rn(acc, __shfl_down_sync(0xffffffffu, acc, off));
    if (lane == 0) g_esq[w] = acc;
}

// ---------------------------------------------------------------------------
// fp32 NT GEMM:  C[M,N] = scale * A[M,512] * B[N,512]^T
// Single fp32 accumulator per element, FFMA, k strictly ascending
// (bitwise-matches cuBLAS-style accumulation for the depth-0 u).
// ---------------------------------------------------------------------------
__device__ __forceinline__ void gemm_body(const float* __restrict__ A,
                                          const float* __restrict__ B,
                                          float* __restrict__ C,
                                          float scale, int N) {
    __shared__ float As[16][128];
    __shared__ float Bs[16][128];
    int tid = threadIdx.x;
    long row0 = (long)blockIdx.y * 128;
    int  col0 = blockIdx.x * 128;
    int tx = tid & 15, ty = tid >> 4;
    float acc[8][8];
#pragma unroll
    for (int i = 0; i < 8; i++)
#pragma unroll
        for (int j = 0; j < 8; j++) acc[i][j] = 0.f;

    const float* Ab = A + row0 * 512;
    const float* Bb = B + (long)col0 * 512;
    int r0 = tid >> 2, c4 = tid & 3;

    for (int k0 = 0; k0 < 512; k0 += 16) {
#pragma unroll
        for (int t = 0; t < 2; t++) {
            int r = r0 + t * 64;
            float4 va = *(const float4*)(Ab + (long)r * 512 + k0 + c4 * 4);
            As[c4 * 4 + 0][r] = va.x; As[c4 * 4 + 1][r] = va.y;
            As[c4 * 4 + 2][r] = va.z; As[c4 * 4 + 3][r] = va.w;
            float4 vb = *(const float4*)(Bb + (long)r * 512 + k0 + c4 * 4);
            Bs[c4 * 4 + 0][r] = vb.x; Bs[c4 * 4 + 1][r] = vb.y;
            Bs[c4 * 4 + 2][r] = vb.z; Bs[c4 * 4 + 3][r] = vb.w;
        }
        __syncthreads();
#pragma unroll
        for (int kk = 0; kk < 16; kk++) {
            float ra[8], rb[8];
            *(float4*)(ra)     = *(const float4*)&As[kk][ty * 8];
            *(float4*)(ra + 4) = *(const float4*)&As[kk][ty * 8 + 4];
            *(float4*)(rb)     = *(const float4*)&Bs[kk][tx * 8];
            *(float4*)(rb + 4) = *(const float4*)&Bs[kk][tx * 8 + 4];
#pragma unroll
            for (int i = 0; i < 8; i++)
#pragma unroll
                for (int j = 0; j < 8; j++) acc[i][j] += ra[i] * rb[j];
        }
        __syncthreads();
    }
#pragma unroll
    for (int i = 0; i < 8; i++) {
        long r = row0 + ty * 8 + i;
#pragma unroll
        for (int j = 0; j < 8; j += 4) {
            float4 v;
            v.x = scale * acc[i][j];     v.y = scale * acc[i][j + 1];
            v.z = scale * acc[i][j + 2]; v.w = scale * acc[i][j + 3];
            *(float4*)(C + r * N + col0 + tx * 8 + j) = v;
        }
    }
}

__global__ __launch_bounds__(256) void gemm_gram_kernel(const float* __restrict__ emb) {
    gemm_body(emb, emb, g_G2, 2.f, NE);          // G2 = 2 E E^T   (grid 8x8)
}
__global__ __launch_bounds__(256) void gemm_u_kernel(const float* __restrict__ emb) {
    gemm_body(g_zf, emb, g_u, 2.f, NE);          // U = 2 zf E^T   (grid 8x512)
}

// ---------------------------------------------------------------------------
// VQ depth loop with exact refinement.
//  approx: d_j = fl(fl(rsq+esq_j) - u_approx_j), u via Gram recursion.
//  shortlist: d_approx <= dmin + 3e-4 (>= 5 ulps of 512, >> all approx error).
//  refine: exact cuBLAS-equivalent u_j = 2 * seq-FFMA(resid, e_j) over k=0..511,
//          lexicographic (d, j) min == reference argmin with first-index ties.
// ---------------------------------------------------------------------------
__global__ __launch_bounds__(256) void vq_kernel(const float* __restrict__ emb,
                                                 float* __restrict__ out) {
    __shared__ float u[NE];
    __shared__ float esq_s[NE];
    __shared__ float resid[EDIM];
    __shared__ float rv[256];
    __shared__ float s_rsq;
    __shared__ int s_cnt;
    __shared__ int s_cand[CAND_CAP];
    __shared__ unsigned long long s_best;

    int n = blockIdx.x;
    int tid = threadIdx.x;
    long ubase = (long)n * NE;
    for (int j = tid; j < NE; j += 256) { u[j] = g_u[ubase + j]; esq_s[j] = g_esq[j]; }
    for (int d = tid; d < EDIM; d += 256) resid[d] = g_zf[(long)n * EDIM + d];
    __syncthreads();

    int idxs[VQ_DEPTH];
#pragma unroll 1
    for (int t = 0; t < VQ_DEPTH; t++) {
        // rsq (order harmless); warp 1's leader resets shortlist state
        if (tid < 32) {
            float acc = 0.f;
            for (int i = tid; i < EDIM; i += 32)
                acc = __fadd_rn(acc, __fmul_rn(resid[i], resid[i]));
            for (int off = 16; off; off >>= 1)
                acc = __fadd_rn(acc, __shfl_down_sync(0xffffffffu, acc, off));
            if (tid == 0) s_rsq = acc;
        }
        if (tid == 32) { s_cnt = 0; s_best = ~0ULL; }
        __syncthreads();
        float rsq = s_rsq;

        float dloc[4];
        float dmin = 3.4e38f;
#pragma unroll
        for (int jj = 0; jj < 4; jj++) {
            int j = tid + jj * 256;
            float q = __fsub_rn(__fadd_rn(rsq, esq_s[j]), u[j]);
            dloc[jj] = q;
            dmin = fminf(dmin, q);
        }
        rv[tid] = dmin;
        __syncthreads();
        for (int off = 128; off; off >>= 1) {
            if (tid < off) rv[tid] = fminf(rv[tid], rv[tid + off]);
            __syncthreads();
        }
        float thr = rv[0] + 3.0e-4f;
        __syncthreads();

#pragma unroll
        for (int jj = 0; jj < 4; jj++) {
            if (dloc[jj] <= thr) {
                int p = atomicAdd(&s_cnt, 1);
                if (p < CAND_CAP) s_cand[p] = tid + jj * 256;
            }
        }
        __syncthreads();

        int cnt = s_cnt < CAND_CAP ? s_cnt : CAND_CAP;
        if (tid < cnt) {
            int j = s_cand[tid];
            const float* ej = emb + (long)j * EDIM;
            float acc = 0.f;
#pragma unroll 8
            for (int k = 0; k < EDIM; k++)
                acc = __fmaf_rn(resid[k], ej[k], acc);      // exact seq-k FFMA chain
            float dex = __fsub_rn(__fadd_rn(rsq, esq_s[j]), __fadd_rn(acc, acc));
            unsigned long long key =
                ((unsigned long long)__float_as_uint(dex) << 32) | (unsigned)j;
            atomicMin(&s_best, key);
        }
        __syncthreads();
        int id = (int)(unsigned)(s_best & 0xffffffffULL);
        idxs[t] = id;

        if (t < VQ_DEPTH - 1) {
            const float* g2 = g_G2 + (long)id * NE;
            for (int j = tid; j < NE; j += 256) u[j] = __fsub_rn(u[j], g2[j]);
            const float* er = emb + (long)id * EDIM;
            for (int d = tid; d < EDIM; d += 256) resid[d] = __fsub_rn(resid[d], er[d]);
        }
        __syncthreads();
    }

    if (tid < VQ_DEPTH)
        out[33554433 + tid * N_ROWS + n] = (float)idxs[tid];

    int b = n >> 14, hb = (n >> 7) & 127, wb = n & 127;
    float lp = 0.f;
    for (int d = tid; d < EDIM; d += 256) {
        float zq = 0.f;
#pragma unroll
        for (int t = 0; t < VQ_DEPTH; t++)
            zq = __fadd_rn(zq, emb[(long)idxs[t] * EDIM + d]);
        float zf = g_zf[(long)n * EDIM + d];
        float zq_st = __fadd_rn(zf, __fsub_rn(zq, zf));   // straight-through
        int c = d >> 2, ki = (d >> 1) & 1, kj = d & 1;
        out[(((b << 7) + c) << 16) + (((hb << 1) + ki) << 8) + (wb << 1) + kj] = zq_st;
        float diff = __fsub_rn(zq, zf);
        lp = __fadd_rn(lp, __fmul_rn(diff, diff));
    }
    rv[tid] = lp;
    __syncthreads();
    for (int off = 128; off; off >>= 1) {
        if (tid < off) rv[tid] += rv[tid + off];
        __syncthreads();
    }
    if (tid == 0) g_partial[n] = rv[0];
}

// ---------------------------------------------------------------------------
// loss = mean + BETA*mean = 1.25 * sum / (N*EDIM)
// ---------------------------------------------------------------------------
__global__ void loss_kernel(float* __restrict__ out) {
    __shared__ float sm[256];
    int tid = threadIdx.x;
    float acc = 0.f;
    for (int i = tid; i < N_ROWS; i += 256) acc += g_partial[i];
    sm[tid] = acc;
    __syncthreads();
    for (int off = 128; off; off >>= 1) {
        if (tid < off) sm[tid] += sm[tid + off];
        __syncthreads();
    }
    if (tid == 0) {
        float m = sm[0] / 33554432.0f;
        out[33554432] = __fadd_rn(m, 0.25f * m);
    }
}

// ---------------------------------------------------------------------------
extern "C" void kernel_launch(void* const* d_in, const int* in_sizes, int n_in,
                              void* d_out, int out_size) {
    const float* x   = (const float*)d_in[0];
    const float* emb = (const float*)d_in[1];
    float* out = (float*)d_out;

    unfold_kernel<<<65536, 128>>>(x);
    esq_kernel<<<128, 256>>>(emb);
    { dim3 g(8, 8);   gemm_gram_kernel<<<g, 256>>>(emb); }
    { dim3 g(8, 512); gemm_u_kernel<<<g, 256>>>(emb); }
    vq_kernel<<<N_ROWS, 256>>>(emb, out);
    loss_kernel<<<1, 256>>>(out);
}

// round 3
// speedup vs baseline: 1.0013x; 1.0013x over previous
#include <cuda_runtime.h>

#define N_ROWS 65536
#define EDIM 512
#define NE 1024
#define VQ_DEPTH 6
#define CAND_CAP 32

// Scratch (static __device__ globals: allocation-free per harness rules)
__device__ float g_zf[(size_t)N_ROWS * EDIM];   // 128 MB  unfolded input
__device__ float g_u[(size_t)N_ROWS * NE];      // 256 MB  u_j = 2 * r . e_j (depth-0)
__device__ float g_G2[NE * NE];                 // 4 MB    2 * E E^T (approx only)
__device__ float g_esq[NE];
__device__ float g_partial[N_ROWS];

// ---------------------------------------------------------------------------
// unfold: zf[n][d] = x[b][c][2hb+ki][2wb+kj]; block=(b,c,hb), thread=wb.
// Coalesced float2 reads, float4 writes (d = c*4 + ki*2 + kj contiguous).
// ---------------------------------------------------------------------------
__global__ void unfold_kernel(const float* __restrict__ x) {
    int bid = blockIdx.x;
    int b = bid >> 14, c = (bid >> 7) & 127, hb = bid & 127;
    int wb = threadIdx.x;
    const float* xr = x + (((long)((b << 7) + c)) << 16) + ((long)(hb << 1) << 8);
    float2 r0 = *(const float2*)(xr + wb * 2);
    float2 r1 = *(const float2*)(xr + 256 + wb * 2);
    long n = ((long)((b << 7) + hb) << 7) + wb;
    float4 v; v.x = r0.x; v.y = r0.y; v.z = r1.x; v.w = r1.y;
    *(float4*)(g_zf + n * EDIM + c * 4) = v;
}

// ---------------------------------------------------------------------------
// e_sq (exact order irrelevant — uniform-shift argument makes rsq/esq ulp
// discrepancies vs XLA harmless; just needs consistency within this kernel).
// ---------------------------------------------------------------------------
__global__ void esq_kernel(const float* __restrict__ emb) {
    int w = (blockIdx.x * blockDim.x + threadIdx.x) >> 5;  // row 0..1023
    int lane = threadIdx.x & 31;
    const float* e = emb + w * EDIM;
    float acc = 0.f;
    for (int i = lane; i < EDIM; i += 32)
        acc = __fadd_rn(acc, __fmul_rn(e[i], e[i]));
    for (int off = 16; off; off >>= 1)
        acc = __fadd_rn(acc, __shfl_down_sync(0xffffffffu, acc, off));
    if (lane == 0) g_esq[w] = acc;
}

// ---------------------------------------------------------------------------
// fp32 NT GEMM:  C[M,N] = scale * A[M,512] * B[N,512]^T
// Single fp32 accumulator per element, FFMA, k strictly ascending
// (bitwise-matches cuBLAS-style accumulation for the depth-0 u).
// ---------------------------------------------------------------------------
__device__ __forceinline__ void gemm_body(const float* __restrict__ A,
                                          const float* __restrict__ B,
                                          float* __restrict__ C,
                                          float scale, int N) {
    __shared__ float As[16][128];
    __shared__ float Bs[16][128];
    int tid = threadIdx.x;
    long row0 = (long)blockIdx.y * 128;
    int  col0 = blockIdx.x * 128;
    int tx = tid & 15, ty = tid >> 4;
    float acc[8][8];
#pragma unroll
    for (int i = 0; i < 8; i++)
#pragma unroll
        for (int j = 0; j < 8; j++) acc[i][j] = 0.f;

    const float* Ab = A + row0 * 512;
    const float* Bb = B + (long)col0 * 512;
    int r0 = tid >> 2, c4 = tid & 3;

    for (int k0 = 0; k0 < 512; k0 += 16) {
#pragma unroll
        for (int t = 0; t < 2; t++) {
            int r = r0 + t * 64;
            float4 va = *(const float4*)(Ab + (long)r * 512 + k0 + c4 * 4);
            As[c4 * 4 + 0][r] = va.x; As[c4 * 4 + 1][r] = va.y;
            As[c4 * 4 + 2][r] = va.z; As[c4 * 4 + 3][r] = va.w;
            float4 vb = *(const float4*)(Bb + (long)r * 512 + k0 + c4 * 4);
            Bs[c4 * 4 + 0][r] = vb.x; Bs[c4 * 4 + 1][r] = vb.y;
            Bs[c4 * 4 + 2][r] = vb.z; Bs[c4 * 4 + 3][r] = vb.w;
        }
        __syncthreads();
#pragma unroll
        for (int kk = 0; kk < 16; kk++) {
            float ra[8], rb[8];
            *(float4*)(ra)     = *(const float4*)&As[kk][ty * 8];
            *(float4*)(ra + 4) = *(const float4*)&As[kk][ty * 8 + 4];
            *(float4*)(rb)     = *(const float4*)&Bs[kk][tx * 8];
            *(float4*)(rb + 4) = *(const float4*)&Bs[kk][tx * 8 + 4];
#pragma unroll
            for (int i = 0; i < 8; i++)
#pragma unroll
                for (int j = 0; j < 8; j++) acc[i][j] += ra[i] * rb[j];
        }
        __syncthreads();
    }
#pragma unroll
    for (int i = 0; i < 8; i++) {
        long r = row0 + ty * 8 + i;
#pragma unroll
        for (int j = 0; j < 8; j += 4) {
            float4 v;
            v.x = scale * acc[i][j];     v.y = scale * acc[i][j + 1];
            v.z = scale * acc[i][j + 2]; v.w = scale * acc[i][j + 3];
            *(float4*)(C + r * N + col0 + tx * 8 + j) = v;
        }
    }
}

__global__ __launch_bounds__(256) void gemm_gram_kernel(const float* __restrict__ emb) {
    gemm_body(emb, emb, g_G2, 2.f, NE);          // G2 = 2 E E^T   (grid 8x8)
}
__global__ __launch_bounds__(256) void gemm_u_kernel(const float* __restrict__ emb) {
    gemm_body(g_zf, emb, g_u, 2.f, NE);          // U = 2 zf E^T   (grid 8x512)
}

// ---------------------------------------------------------------------------
// VQ depth loop with exact refinement.
//  approx: d_j = fl(fl(rsq+esq_j) - u_approx_j), u via Gram recursion.
//  shortlist: d_approx <= dmin + 3e-4 (>= 5 ulps of 512, >> all approx error).
//  refine: exact cuBLAS-equivalent u_j = 2 * seq-FFMA(resid, e_j) over k=0..511,
//          lexicographic (d, j) min == reference argmin with first-index ties.
// ---------------------------------------------------------------------------
__global__ __launch_bounds__(256) void vq_kernel(const float* __restrict__ emb,
                                                 float* __restrict__ out) {
    __shared__ float u[NE];
    __shared__ float esq_s[NE];
    __shared__ float resid[EDIM];
    __shared__ float rv[256];
    __shared__ float s_rsq;
    __shared__ int s_cnt;
    __shared__ int s_cand[CAND_CAP];
    __shared__ unsigned long long s_best;

    int n = blockIdx.x;
    int tid = threadIdx.x;
    long ubase = (long)n * NE;
    for (int j = tid; j < NE; j += 256) { u[j] = g_u[ubase + j]; esq_s[j] = g_esq[j]; }
    for (int d = tid; d < EDIM; d += 256) resid[d] = g_zf[(long)n * EDIM + d];
    __syncthreads();

    int idxs[VQ_DEPTH];
#pragma unroll 1
    for (int t = 0; t < VQ_DEPTH; t++) {
        // rsq (order harmless); warp 1's leader resets shortlist state
        if (tid < 32) {
            float acc = 0.f;
            for (int i = tid; i < EDIM; i += 32)
                acc = __fadd_rn(acc, __fmul_rn(resid[i], resid[i]));
            for (int off = 16; off; off >>= 1)
                acc = __fadd_rn(acc, __shfl_down_sync(0xffffffffu, acc, off));
            if (tid == 0) s_rsq = acc;
        }
        if (tid == 32) { s_cnt = 0; s_best = ~0ULL; }
        __syncthreads();
        float rsq = s_rsq;

        float dloc[4];
        float dmin = 3.4e38f;
#pragma unroll
        for (int jj = 0; jj < 4; jj++) {
            int j = tid + jj * 256;
            float q = __fsub_rn(__fadd_rn(rsq, esq_s[j]), u[j]);
            dloc[jj] = q;
            dmin = fminf(dmin, q);
        }
        rv[tid] = dmin;
        __syncthreads();
        for (int off = 128; off; off >>= 1) {
            if (tid < off) rv[tid] = fminf(rv[tid], rv[tid + off]);
            __syncthreads();
        }
        float thr = rv[0] + 3.0e-4f;
        __syncthreads();

#pragma unroll
        for (int jj = 0; jj < 4; jj++) {
            if (dloc[jj] <= thr) {
                int p = atomicAdd(&s_cnt, 1);
                if (p < CAND_CAP) s_cand[p] = tid + jj * 256;
            }
        }
        __syncthreads();

        int cnt = s_cnt < CAND_CAP ? s_cnt : CAND_CAP;
        if (tid < cnt) {
            int j = s_cand[tid];
            const float* ej = emb + (long)j * EDIM;
            float acc = 0.f;
#pragma unroll 8
            for (int k = 0; k < EDIM; k++)
                acc = __fmaf_rn(resid[k], ej[k], acc);      // exact seq-k FFMA chain
            float dex = __fsub_rn(__fadd_rn(rsq, esq_s[j]), __fadd_rn(acc, acc));
            unsigned long long key =
                ((unsigned long long)__float_as_uint(dex) << 32) | (unsigned)j;
            atomicMin(&s_best, key);
        }
        __syncthreads();
        int id = (int)(unsigned)(s_best & 0xffffffffULL);
        idxs[t] = id;

        if (t < VQ_DEPTH - 1) {
            const float* g2 = g_G2 + (long)id * NE;
            for (int j = tid; j < NE; j += 256) u[j] = __fsub_rn(u[j], g2[j]);
            const float* er = emb + (long)id * EDIM;
            for (int d = tid; d < EDIM; d += 256) resid[d] = __fsub_rn(resid[d], er[d]);
        }
        __syncthreads();
    }

    if (tid < VQ_DEPTH)
        out[33554433 + tid * N_ROWS + n] = (float)idxs[tid];

    int b = n >> 14, hb = (n >> 7) & 127, wb = n & 127;
    float lp = 0.f;
    for (int d = tid; d < EDIM; d += 256) {
        float zq = 0.f;
#pragma unroll
        for (int t = 0; t < VQ_DEPTH; t++)
            zq = __fadd_rn(zq, emb[(long)idxs[t] * EDIM + d]);
        float zf = g_zf[(long)n * EDIM + d];
        float zq_st = __fadd_rn(zf, __fsub_rn(zq, zf));   // straight-through
        int c = d >> 2, ki = (d >> 1) & 1, kj = d & 1;
        out[(((b << 7) + c) << 16) + (((hb << 1) + ki) << 8) + (wb << 1) + kj] = zq_st;
        float diff = __fsub_rn(zq, zf);
        lp = __fadd_rn(lp, __fmul_rn(diff, diff));
    }
    rv[tid] = lp;
    __syncthreads();
    for (int off = 128; off; off >>= 1) {
        if (tid < off) rv[tid] += rv[tid + off];
        __syncthreads();
    }
    if (tid == 0) g_partial[n] = rv[0];
}

// ---------------------------------------------------------------------------
// loss = mean + BETA*mean = 1.25 * sum / (N*EDIM)
// ---------------------------------------------------------------------------
__global__ void loss_kernel(float* __restrict__ out) {
    __shared__ float sm[256];
    int tid = threadIdx.x;
    float acc = 0.f;
    for (int i = tid; i < N_ROWS; i += 256) acc += g_partial[i];
    sm[tid] = acc;
    __syncthreads();
    for (int off = 128; off; off >>= 1) {
        if (tid < off) sm[tid] += sm[tid + off];
        __syncthreads();
    }
    if (tid == 0) {
        float m = sm[0] / 33554432.0f;
        out[33554432] = __fadd_rn(m, 0.25f * m);
    }
}

// ---------------------------------------------------------------------------
extern "C" void kernel_launch(void* const* d_in, const int* in_sizes, int n_in,
                              void* d_out, int out_size) {
    const float* x   = (const float*)d_in[0];
    const float* emb = (const float*)d_in[1];
    float* out = (float*)d_out;

    unfold_kernel<<<65536, 128>>>(x);
    esq_kernel<<<128, 256>>>(emb);
    { dim3 g(8, 8);   gemm_gram_kernel<<<g, 256>>>(emb); }
    { dim3 g(8, 512); gemm_u_kernel<<<g, 256>>>(emb); }
    vq_kernel<<<N_ROWS, 256>>>(emb, out);
    loss_kernel<<<1, 256>>>(out);
}

// round 4
// speedup vs baseline: 1.0136x; 1.0123x over previous
#include <cuda_runtime.h>
#include <cuda_bf16.h>

#define N_ROWS 65536
#define EDIM 512
#define NE 1024
#define VQ_DEPTH 6

// Scratch (static __device__ globals: allocation-free per harness rules)
__device__ float g_zf[(size_t)N_ROWS * EDIM];            // 128 MB unfolded (fp32, exact)
__device__ __nv_bfloat16 g_zf_bf[(size_t)N_ROWS * EDIM]; // 64 MB  bf16 copy for MMA
__device__ __nv_bfloat16 g_emb_bf[NE * EDIM];            // 1 MB
__device__ float g_u[(size_t)N_ROWS * NE];               // 256 MB u0 = 2 r.e (approx ok)
__device__ float g_G2[NE * NE];                          // 4 MB   2 E E^T (approx ok)
__device__ float g_esq[NE];
__device__ float g_partial[N_ROWS];

// ---------------------------------------------------------------------------
// unfold: zf[n][d] = x[b][c][2hb+ki][2wb+kj]; also emit bf16 copy for MMA.
// ---------------------------------------------------------------------------
__global__ void unfold_kernel(const float* __restrict__ x) {
    int bid = blockIdx.x;
    int b = bid >> 14, c = (bid >> 7) & 127, hb = bid & 127;
    int wb = threadIdx.x;
    const float* xr = x + (((long)((b << 7) + c)) << 16) + ((long)(hb << 1) << 8);
    float2 r0 = *(const float2*)(xr + wb * 2);
    float2 r1 = *(const float2*)(xr + 256 + wb * 2);
    long n = ((long)((b << 7) + hb) << 7) + wb;
    float4 v; v.x = r0.x; v.y = r0.y; v.z = r1.x; v.w = r1.y;
    *(float4*)(g_zf + n * EDIM + c * 4) = v;
    __nv_bfloat162 p0, p1;
    p0.x = __float2bfloat16(v.x); p0.y = __float2bfloat16(v.y);
    p1.x = __float2bfloat16(v.z); p1.y = __float2bfloat16(v.w);
    *(__nv_bfloat162*)(g_zf_bf + n * EDIM + c * 4)     = p0;
    *(__nv_bfloat162*)(g_zf_bf + n * EDIM + c * 4 + 2) = p1;
}

__global__ void emb_bf_kernel(const float* __restrict__ emb) {
    int i = blockIdx.x * 256 + threadIdx.x;   // 2048 blocks cover 524288
    g_emb_bf[i] = __float2bfloat16(emb[i]);
}

// ---------------------------------------------------------------------------
// e_sq (ulp-level discrepancies vs XLA are harmless: uniform grid-shift).
// ---------------------------------------------------------------------------
__global__ void esq_kernel(const float* __restrict__ emb) {
    int w = (blockIdx.x * blockDim.x + threadIdx.x) >> 5;
    int lane = threadIdx.x & 31;
    const float* e = emb + w * EDIM;
    float acc = 0.f;
    for (int i = lane; i < EDIM; i += 32)
        acc = __fadd_rn(acc, __fmul_rn(e[i], e[i]));
    for (int off = 16; off; off >>= 1)
        acc = __fadd_rn(acc, __shfl_down_sync(0xffffffffu, acc, off));
    if (lane == 0) g_esq[w] = acc;
}

// ---------------------------------------------------------------------------
// fp32 SIMT GEMM kept only for the small Gram matrix G2 = 2 E E^T.
// ---------------------------------------------------------------------------
__global__ __launch_bounds__(256) void gemm_gram_kernel(const float* __restrict__ emb) {
    __shared__ float As[16][128];
    __shared__ float Bs[16][128];
    int tid = threadIdx.x;
    long row0 = (long)blockIdx.y * 128;
    int  col0 = blockIdx.x * 128;
    int tx = tid & 15, ty = tid >> 4;
    float acc[8][8];
#pragma unroll
    for (int i = 0; i < 8; i++)
#pragma unroll
        for (int j = 0; j < 8; j++) acc[i][j] = 0.f;
    const float* Ab = emb + row0 * 512;
    const float* Bb = emb + (long)col0 * 512;
    int r0 = tid >> 2, c4 = tid & 3;
    for (int k0 = 0; k0 < 512; k0 += 16) {
#pragma unroll
        for (int t = 0; t < 2; t++) {
            int r = r0 + t * 64;
            float4 va = *(const float4*)(Ab + (long)r * 512 + k0 + c4 * 4);
            As[c4 * 4 + 0][r] = va.x; As[c4 * 4 + 1][r] = va.y;
            As[c4 * 4 + 2][r] = va.z; As[c4 * 4 + 3][r] = va.w;
            float4 vb = *(const float4*)(Bb + (long)r * 512 + k0 + c4 * 4);
            Bs[c4 * 4 + 0][r] = vb.x; Bs[c4 * 4 + 1][r] = vb.y;
            Bs[c4 * 4 + 2][r] = vb.z; Bs[c4 * 4 + 3][r] = vb.w;
        }
        __syncthreads();
#pragma unroll
        for (int kk = 0; kk < 16; kk++) {
            float ra[8], rb[8];
            *(float4*)(ra)     = *(const float4*)&As[kk][ty * 8];
            *(float4*)(ra + 4) = *(const float4*)&As[kk][ty * 8 + 4];
            *(float4*)(rb)     = *(const float4*)&Bs[kk][tx * 8];
            *(float4*)(rb + 4) = *(const float4*)&Bs[kk][tx * 8 + 4];
#pragma unroll
            for (int i = 0; i < 8; i++)
#pragma unroll
                for (int j = 0; j < 8; j++) acc[i][j] += ra[i] * rb[j];
        }
        __syncthreads();
    }
#pragma unroll
    for (int i = 0; i < 8; i++) {
        long r = row0 + ty * 8 + i;
#pragma unroll
        for (int j = 0; j < 8; j += 4) {
            float4 v;
            v.x = 2.f * acc[i][j];     v.y = 2.f * acc[i][j + 1];
            v.z = 2.f * acc[i][j + 2]; v.w = 2.f * acc[i][j + 3];
            *(float4*)(g_G2 + r * NE + col0 + tx * 8 + j) = v;
        }
    }
}

// ---------------------------------------------------------------------------
// Tensor-core GEMM: g_u[M=65536,N=1024] = 2 * zf_bf[M,512] @ emb_bf[N,512]^T
// mma.sync.m16n8k16 bf16->fp32. Tile 128x128x32, 8 warps (warp tile 32x64),
// cp.async double buffering, ldmatrix from 80B-strided smem (conflict-free).
// ---------------------------------------------------------------------------
#define SMSTRIDE 40   // bf16 elems per smem row (80 B): 20-word stride => distinct banks

__device__ __forceinline__ unsigned smaddr(const void* p) {
    return (unsigned)__cvta_generic_to_shared(p);
}
#define CP16(dst, src) \
    asm volatile("cp.async.cg.shared.global [%0], [%1], 16;" :: "r"(dst), "l"(src))

__device__ __forceinline__ void mma16816(float* c, const unsigned* a,
                                         unsigned b0, unsigned b1) {
    asm volatile(
        "mma.sync.aligned.m16n8k16.row.col.f32.bf16.bf16.f32 "
        "{%0,%1,%2,%3}, {%4,%5,%6,%7}, {%8,%9}, {%0,%1,%2,%3};"
        : "+f"(c[0]), "+f"(c[1]), "+f"(c[2]), "+f"(c[3])
        : "r"(a[0]), "r"(a[1]), "r"(a[2]), "r"(a[3]), "r"(b0), "r"(b1));
}

__global__ __launch_bounds__(256) void gemm_u_mma(void) {
    __shared__ __nv_bfloat16 sA[2][128 * SMSTRIDE];
    __shared__ __nv_bfloat16 sB[2][128 * SMSTRIDE];
    int tid = threadIdx.x;
    int wid = tid >> 5, lane = tid & 31;
    int warp_m = wid & 3, warp_n = wid >> 2;
    long row0 = (long)blockIdx.y * 128;
    int  col0 = blockIdx.x * 128;

    const __nv_bfloat16* Ag = g_zf_bf + row0 * 512;
    const __nv_bfloat16* Bg = g_emb_bf + (long)col0 * 512;

    int lrow = tid >> 2, lchk = tid & 3;     // each thread: rows lrow, lrow+64; 16B chunk

    float acc[2][8][4];
#pragma unroll
    for (int i = 0; i < 2; i++)
#pragma unroll
        for (int j = 0; j < 8; j++)
#pragma unroll
            for (int q = 0; q < 4; q++) acc[i][j][q] = 0.f;

#define STAGE_LOAD(st, k0)                                                      \
    {                                                                           \
        _Pragma("unroll")                                                       \
        for (int h = 0; h < 2; h++) {                                           \
            int r = lrow + h * 64;                                              \
            CP16(smaddr(&sA[st][r * SMSTRIDE + lchk * 8]),                      \
                 Ag + (long)r * 512 + (k0) + lchk * 8);                         \
            CP16(smaddr(&sB[st][r * SMSTRIDE + lchk * 8]),                      \
                 Bg + (long)r * 512 + (k0) + lchk * 8);                         \
        }                                                                       \
        asm volatile("cp.async.commit_group;");                                 \
    }

    STAGE_LOAD(0, 0);

    int lr8  = (lane & 7) + ((lane >> 3) & 1) * 8;   // row within 16-row frag
    int lc8  = ((lane >> 4) & 1) * 8;                // 8-elem (16B) k sub-chunk

#pragma unroll 1
    for (int it = 0; it < 16; it++) {
        if (it < 15) {
            STAGE_LOAD((it + 1) & 1, (it + 1) * 32);
            asm volatile("cp.async.wait_group 1;" ::: "memory");
        } else {
            asm volatile("cp.async.wait_group 0;" ::: "memory");
        }
        __syncthreads();
        int st = it & 1;
#pragma unroll
        for (int ks = 0; ks < 2; ks++) {
            unsigned a[2][4];
#pragma unroll
            for (int mt = 0; mt < 2; mt++) {
                unsigned ad = smaddr(&sA[st][(warp_m * 32 + mt * 16 + lr8) * SMSTRIDE
                                             + ks * 16 + lc8]);
                asm volatile("ldmatrix.sync.aligned.m8n8.x4.shared.b16 "
                             "{%0,%1,%2,%3}, [%4];"
                             : "=r"(a[mt][0]), "=r"(a[mt][1]),
                               "=r"(a[mt][2]), "=r"(a[mt][3]) : "r"(ad));
            }
#pragma unroll
            for (int g = 0; g < 4; g++) {
                unsigned r0, r1, r2, r3;
                unsigned bd = smaddr(&sB[st][(warp_n * 64 + g * 16 + lr8) * SMSTRIDE
                                             + ks * 16 + lc8]);
                asm volatile("ldmatrix.sync.aligned.m8n8.x4.shared.b16 "
                             "{%0,%1,%2,%3}, [%4];"
                             : "=r"(r0), "=r"(r1), "=r"(r2), "=r"(r3) : "r"(bd));
#pragma unroll
                for (int mt = 0; mt < 2; mt++) {
                    mma16816(acc[mt][g * 2 + 0], a[mt], r0, r2);
                    mma16816(acc[mt][g * 2 + 1], a[mt], r1, r3);
                }
            }
        }
        __syncthreads();
    }

    // epilogue: C = 2*acc
#pragma unroll
    for (int mt = 0; mt < 2; mt++) {
#pragma unroll
        for (int nt = 0; nt < 8; nt++) {
            long m = row0 + warp_m * 32 + mt * 16 + (lane >> 2);
            int  n = col0 + warp_n * 64 + nt * 8 + (lane & 3) * 2;
            float2 v0, v1;
            v0.x = 2.f * acc[mt][nt][0]; v0.y = 2.f * acc[mt][nt][1];
            v1.x = 2.f * acc[mt][nt][2]; v1.y = 2.f * acc[mt][nt][3];
            *(float2*)(g_u + m * NE + n)       = v0;
            *(float2*)(g_u + (m + 8) * NE + n) = v1;
        }
    }
}

// ---------------------------------------------------------------------------
// VQ depth loop: approx scores (bf16-GEMM u0 + fp32 Gram recursion) shortlist
// within 4e-3 (> 2x worst-case approx error); exact cuBLAS-order seq-FFMA
// refine; lexicographic (d, j) min == reference argmin w/ first-index ties.
// ---------------------------------------------------------------------------
__global__ __launch_bounds__(256) void vq_kernel(const float* __restrict__ emb,
                                                 float* __restrict__ out) {
    __shared__ float u[NE];
    __shared__ float esq_s[NE];
    __shared__ float resid[EDIM];
    __shared__ float rv[256];
    __shared__ float s_rsq;
    __shared__ unsigned long long s_best;

    int n = blockIdx.x;
    int tid = threadIdx.x;
    long ubase = (long)n * NE;
    for (int j = tid; j < NE; j += 256) { u[j] = g_u[ubase + j]; esq_s[j] = g_esq[j]; }
    for (int d = tid; d < EDIM; d += 256) resid[d] = g_zf[(long)n * EDIM + d];
    __syncthreads();

    int idxs[VQ_DEPTH];
#pragma unroll 1
    for (int t = 0; t < VQ_DEPTH; t++) {
        if (tid < 32) {
            float acc = 0.f;
            for (int i = tid; i < EDIM; i += 32)
                acc = __fadd_rn(acc, __fmul_rn(resid[i], resid[i]));
            for (int off = 16; off; off >>= 1)
                acc = __fadd_rn(acc, __shfl_down_sync(0xffffffffu, acc, off));
            if (tid == 0) s_rsq = acc;
        }
        if (tid == 32) s_best = ~0ULL;
        __syncthreads();
        float rsq = s_rsq;

        float dloc[4];
        float dmin = 3.4e38f;
#pragma unroll
        for (int jj = 0; jj < 4; jj++) {
            int j = tid + jj * 256;
            float q = __fsub_rn(__fadd_rn(rsq, esq_s[j]), u[j]);
            dloc[jj] = q;
            dmin = fminf(dmin, q);
        }
        rv[tid] = dmin;
        __syncthreads();
        for (int off = 128; off; off >>= 1) {
            if (tid < off) rv[tid] = fminf(rv[tid], rv[tid + off]);
            __syncthreads();
        }
        float thr = rv[0] + 4.0e-3f;
        __syncthreads();

#pragma unroll
        for (int jj = 0; jj < 4; jj++) {
            if (dloc[jj] <= thr) {
                int j = tid + jj * 256;
                const float* ej = emb + (long)j * EDIM;
                float acc = 0.f;
#pragma unroll 8
                for (int k = 0; k < EDIM; k++)
                    acc = __fmaf_rn(resid[k], ej[k], acc);   // exact seq-k FFMA chain
                float dex = __fsub_rn(__fadd_rn(rsq, esq_s[j]), __fadd_rn(acc, acc));
                unsigned long long key =
                    ((unsigned long long)__float_as_uint(dex) << 32) | (unsigned)j;
                atomicMin(&s_best, key);
            }
        }
        __syncthreads();
        int id = (int)(unsigned)(s_best & 0xffffffffULL);
        idxs[t] = id;

        if (t < VQ_DEPTH - 1) {
            const float* g2 = g_G2 + (long)id * NE;
            for (int j = tid; j < NE; j += 256) u[j] = __fsub_rn(u[j], g2[j]);
            const float* er = emb + (long)id * EDIM;
            for (int d = tid; d < EDIM; d += 256) resid[d] = __fsub_rn(resid[d], er[d]);
        }
        __syncthreads();
    }

    if (tid < VQ_DEPTH)
        out[33554433 + tid * N_ROWS + n] = (float)idxs[tid];

    int b = n >> 14, hb = (n >> 7) & 127, wb = n & 127;
    float lp = 0.f;
    for (int d = tid; d < EDIM; d += 256) {
        float zq = 0.f;
#pragma unroll
        for (int t = 0; t < VQ_DEPTH; t++)
            zq = __fadd_rn(zq, emb[(long)idxs[t] * EDIM + d]);
        float zf = g_zf[(long)n * EDIM + d];
        float zq_st = __fadd_rn(zf, __fsub_rn(zq, zf));
        int c = d >> 2, ki = (d >> 1) & 1, kj = d & 1;
        out[(((b << 7) + c) << 16) + (((hb << 1) + ki) << 8) + (wb << 1) + kj] = zq_st;
        float diff = __fsub_rn(zq, zf);
        lp = __fadd_rn(lp, __fmul_rn(diff, diff));
    }
    rv[tid] = lp;
    __syncthreads();
    for (int off = 128; off; off >>= 1) {
        if (tid < off) rv[tid] += rv[tid + off];
        __syncthreads();
    }
    if (tid == 0) g_partial[n] = rv[0];
}

// ---------------------------------------------------------------------------
__global__ void loss_kernel(float* __restrict__ out) {
    __shared__ float sm[256];
    int tid = threadIdx.x;
    float acc = 0.f;
    for (int i = tid; i < N_ROWS; i += 256) acc += g_partial[i];
    sm[tid] = acc;
    __syncthreads();
    for (int off = 128; off; off >>= 1) {
        if (tid < off) sm[tid] += sm[tid + off];
        __syncthreads();
    }
    if (tid == 0) {
        float m = sm[0] / 33554432.0f;
        out[33554432] = __fadd_rn(m, 0.25f * m);
    }
}

// ---------------------------------------------------------------------------
extern "C" void kernel_launch(void* const* d_in, const int* in_sizes, int n_in,
                              void* d_out, int out_size) {
    const float* x   = (const float*)d_in[0];
    const float* emb = (const float*)d_in[1];
    float* out = (float*)d_out;

    unfold_kernel<<<65536, 128>>>(x);
    emb_bf_kernel<<<2048, 256>>>(emb);
    esq_kernel<<<128, 256>>>(emb);
    { dim3 g(8, 8);   gemm_gram_kernel<<<g, 256>>>(emb); }
    { dim3 g(8, 512); gemm_u_mma<<<g, 256>>>(); }
    vq_kernel<<<N_ROWS, 256>>>(emb, out);
    loss_kernel<<<1, 256>>>(out);
}

// round 5
// speedup vs baseline: 2.7684x; 2.7312x over previous
#include <cuda_runtime.h>
#include <cuda_bf16.h>

#define N_ROWS 65536
#define EDIM 512
#define NE 1024
#define VQ_DEPTH 6
#define CAND_CAP 32
#define MARGIN 6.0e-4f

// Scratch (static __device__ globals: allocation-free per harness rules)
__device__ float g_zf[(size_t)N_ROWS * EDIM];            // 128 MB unfolded (fp32, exact)
__device__ __nv_bfloat16 g_zf_bf[(size_t)N_ROWS * EDIM]; // 64 MB  bf16 copy for MMA
__device__ __nv_bfloat16 g_emb_bf[NE * EDIM];            // 1 MB
__device__ float g_u[(size_t)N_ROWS * NE];               // 256 MB u0 = 2 r.e (approx ok)
__device__ float g_G2[NE * NE];                          // 4 MB   2 E E^T (approx ok)
__device__ float g_esq[NE];
__device__ float g_partial[N_ROWS];

// ---------------------------------------------------------------------------
// unfold: zf[n][d] = x[b][c][2hb+ki][2wb+kj]; also emit bf16 copy for MMA.
// ---------------------------------------------------------------------------
__global__ void unfold_kernel(const float* __restrict__ x) {
    int bid = blockIdx.x;
    int b = bid >> 14, c = (bid >> 7) & 127, hb = bid & 127;
    int wb = threadIdx.x;
    const float* xr = x + (((long)((b << 7) + c)) << 16) + ((long)(hb << 1) << 8);
    float2 r0 = *(const float2*)(xr + wb * 2);
    float2 r1 = *(const float2*)(xr + 256 + wb * 2);
    long n = ((long)((b << 7) + hb) << 7) + wb;
    float4 v; v.x = r0.x; v.y = r0.y; v.z = r1.x; v.w = r1.y;
    *(float4*)(g_zf + n * EDIM + c * 4) = v;
    __nv_bfloat162 p0, p1;
    p0.x = __float2bfloat16(v.x); p0.y = __float2bfloat16(v.y);
    p1.x = __float2bfloat16(v.z); p1.y = __float2bfloat16(v.w);
    *(__nv_bfloat162*)(g_zf_bf + n * EDIM + c * 4)     = p0;
    *(__nv_bfloat162*)(g_zf_bf + n * EDIM + c * 4 + 2) = p1;
}

__global__ void emb_bf_kernel(const float* __restrict__ emb) {
    int i = blockIdx.x * 256 + threadIdx.x;
    g_emb_bf[i] = __float2bfloat16(emb[i]);
}

// ---------------------------------------------------------------------------
__global__ void esq_kernel(const float* __restrict__ emb) {
    int w = (blockIdx.x * blockDim.x + threadIdx.x) >> 5;
    int lane = threadIdx.x & 31;
    const float* e = emb + w * EDIM;
    float acc = 0.f;
    for (int i = lane; i < EDIM; i += 32)
        acc = __fadd_rn(acc, __fmul_rn(e[i], e[i]));
    for (int off = 16; off; off >>= 1)
        acc = __fadd_rn(acc, __shfl_down_sync(0xffffffffu, acc, off));
    if (lane == 0) g_esq[w] = acc;
}

// ---------------------------------------------------------------------------
// fp32 SIMT GEMM for the small Gram matrix G2 = 2 E E^T (1 GFLOP).
// ---------------------------------------------------------------------------
__global__ __launch_bounds__(256) void gemm_gram_kernel(const float* __restrict__ emb) {
    __shared__ float As[16][128];
    __shared__ float Bs[16][128];
    int tid = threadIdx.x;
    long row0 = (long)blockIdx.y * 128;
    int  col0 = blockIdx.x * 128;
    int tx = tid & 15, ty = tid >> 4;
    float acc[8][8];
#pragma unroll
    for (int i = 0; i < 8; i++)
#pragma unroll
        for (int j = 0; j < 8; j++) acc[i][j] = 0.f;
    const float* Ab = emb + row0 * 512;
    const float* Bb = emb + (long)col0 * 512;
    int r0 = tid >> 2, c4 = tid & 3;
    for (int k0 = 0; k0 < 512; k0 += 16) {
#pragma unroll
        for (int t = 0; t < 2; t++) {
            int r = r0 + t * 64;
            float4 va = *(const float4*)(Ab + (long)r * 512 + k0 + c4 * 4);
            As[c4 * 4 + 0][r] = va.x; As[c4 * 4 + 1][r] = va.y;
            As[c4 * 4 + 2][r] = va.z; As[c4 * 4 + 3][r] = va.w;
            float4 vb = *(const float4*)(Bb + (long)r * 512 + k0 + c4 * 4);
            Bs[c4 * 4 + 0][r] = vb.x; Bs[c4 * 4 + 1][r] = vb.y;
            Bs[c4 * 4 + 2][r] = vb.z; Bs[c4 * 4 + 3][r] = vb.w;
        }
        __syncthreads();
#pragma unroll
        for (int kk = 0; kk < 16; kk++) {
            float ra[8], rb[8];
            *(float4*)(ra)     = *(const float4*)&As[kk][ty * 8];
            *(float4*)(ra + 4) = *(const float4*)&As[kk][ty * 8 + 4];
            *(float4*)(rb)     = *(const float4*)&Bs[kk][tx * 8];
            *(float4*)(rb + 4) = *(const float4*)&Bs[kk][tx * 8 + 4];
#pragma unroll
            for (int i = 0; i < 8; i++)
#pragma unroll
                for (int j = 0; j < 8; j++) acc[i][j] += ra[i] * rb[j];
        }
        __syncthreads();
    }
#pragma unroll
    for (int i = 0; i < 8; i++) {
        long r = row0 + ty * 8 + i;
#pragma unroll
        for (int j = 0; j < 8; j += 4) {
            float4 v;
            v.x = 2.f * acc[i][j];     v.y = 2.f * acc[i][j + 1];
            v.z = 2.f * acc[i][j + 2]; v.w = 2.f * acc[i][j + 3];
            *(float4*)(g_G2 + r * NE + col0 + tx * 8 + j) = v;
        }
    }
}

// ---------------------------------------------------------------------------
// Tensor-core GEMM: g_u[65536,1024] = 2 * zf_bf @ emb_bf^T
// mma.sync.m16n8k16, tile 128x128x32, 3-stage cp.async, one sync per iter.
// ---------------------------------------------------------------------------
#define SMSTRIDE 40   // bf16 elems per smem row (80 B) -> conflict-free ldmatrix

__device__ __forceinline__ unsigned smaddr(const void* p) {
    return (unsigned)__cvta_generic_to_shared(p);
}
#define CP16(dst, src) \
    asm volatile("cp.async.cg.shared.global [%0], [%1], 16;" :: "r"(dst), "l"(src))

__device__ __forceinline__ void mma16816(float* c, const unsigned* a,
                                         unsigned b0, unsigned b1) {
    asm volatile(
        "mma.sync.aligned.m16n8k16.row.col.f32.bf16.bf16.f32 "
        "{%0,%1,%2,%3}, {%4,%5,%6,%7}, {%8,%9}, {%0,%1,%2,%3};"
        : "+f"(c[0]), "+f"(c[1]), "+f"(c[2]), "+f"(c[3])
        : "r"(a[0]), "r"(a[1]), "r"(a[2]), "r"(a[3]), "r"(b0), "r"(b1));
}

__global__ __launch_bounds__(256) void gemm_u_mma(void) {
    __shared__ __nv_bfloat16 sA[3][128 * SMSTRIDE];
    __shared__ __nv_bfloat16 sB[3][128 * SMSTRIDE];
    int tid = threadIdx.x;
    int wid = tid >> 5, lane = tid & 31;
    int warp_m = wid & 3, warp_n = wid >> 2;
    long row0 = (long)blockIdx.y * 128;
    int  col0 = blockIdx.x * 128;

    const __nv_bfloat16* Ag = g_zf_bf + row0 * 512;
    const __nv_bfloat16* Bg = g_emb_bf + (long)col0 * 512;

    int lrow = tid >> 2, lchk = tid & 3;

    float acc[2][8][4];
#pragma unroll
    for (int i = 0; i < 2; i++)
#pragma unroll
        for (int j = 0; j < 8; j++)
#pragma unroll
            for (int q = 0; q < 4; q++) acc[i][j][q] = 0.f;

#define STAGE_LOAD(st, k0)                                                      \
    {                                                                           \
        _Pragma("unroll")                                                       \
        for (int h = 0; h < 2; h++) {                                           \
            int r = lrow + h * 64;                                              \
            CP16(smaddr(&sA[st][r * SMSTRIDE + lchk * 8]),                      \
                 Ag + (long)r * 512 + (k0) + lchk * 8);                         \
            CP16(smaddr(&sB[st][r * SMSTRIDE + lchk * 8]),                      \
                 Bg + (long)r * 512 + (k0) + lchk * 8);                         \
        }                                                                       \
        asm volatile("cp.async.commit_group;");                                 \
    }

    STAGE_LOAD(0, 0);
    STAGE_LOAD(1, 32);

    int lr8 = (lane & 7) + ((lane >> 3) & 1) * 8;
    int lc8 = ((lane >> 4) & 1) * 8;

#pragma unroll 1
    for (int it = 0; it < 16; it++) {
        asm volatile("cp.async.wait_group 1;" ::: "memory");
        __syncthreads();
        int st = it % 3;
#pragma unroll
        for (int ks = 0; ks < 2; ks++) {
            unsigned a[2][4];
#pragma unroll
            for (int mt = 0; mt < 2; mt++) {
                unsigned ad = smaddr(&sA[st][(warp_m * 32 + mt * 16 + lr8) * SMSTRIDE
                                             + ks * 16 + lc8]);
                asm volatile("ldmatrix.sync.aligned.m8n8.x4.shared.b16 "
                             "{%0,%1,%2,%3}, [%4];"
                             : "=r"(a[mt][0]), "=r"(a[mt][1]),
                               "=r"(a[mt][2]), "=r"(a[mt][3]) : "r"(ad));
            }
#pragma unroll
            for (int g = 0; g < 4; g++) {
                unsigned r0, r1, r2, r3;
                unsigned bd = smaddr(&sB[st][(warp_n * 64 + g * 16 + lr8) * SMSTRIDE
                                             + ks * 16 + lc8]);
                asm volatile("ldmatrix.sync.aligned.m8n8.x4.shared.b16 "
                             "{%0,%1,%2,%3}, [%4];"
                             : "=r"(r0), "=r"(r1), "=r"(r2), "=r"(r3) : "r"(bd));
#pragma unroll
                for (int mt = 0; mt < 2; mt++) {
                    mma16816(acc[mt][g * 2 + 0], a[mt], r0, r2);
                    mma16816(acc[mt][g * 2 + 1], a[mt], r1, r3);
                }
            }
        }
        if (it + 2 < 16) STAGE_LOAD((it + 2) % 3, (it + 2) * 32);
    }

#pragma unroll
    for (int mt = 0; mt < 2; mt++) {
#pragma unroll
        for (int nt = 0; nt < 8; nt++) {
            long m = row0 + warp_m * 32 + mt * 16 + (lane >> 2);
            int  n = col0 + warp_n * 64 + nt * 8 + (lane & 3) * 2;
            float2 v0, v1;
            v0.x = 2.f * acc[mt][nt][0]; v0.y = 2.f * acc[mt][nt][1];
            v1.x = 2.f * acc[mt][nt][2]; v1.y = 2.f * acc[mt][nt][3];
            *(float2*)(g_u + m * NE + n)       = v0;
            *(float2*)(g_u + (m + 8) * NE + n) = v1;
        }
    }
}

// ---------------------------------------------------------------------------
// VQ depth loop. Approx scores shortlist within 6e-4 (12 sigma of bf16 noise
// + quantization grid); candidates refined with exact cuBLAS-order seq-FFMA
// chains run from SMEM-staged e rows (one candidate per warp, parallel);
// lexicographic (d, j) min == reference argmin with first-index ties.
// ---------------------------------------------------------------------------
__global__ __launch_bounds__(256) void vq_kernel(const float* __restrict__ emb,
                                                 float* __restrict__ out) {
    __shared__ float u[NE];
    __shared__ float esq_s[NE];
    __shared__ float resid[EDIM];
    __shared__ float sEj[8][EDIM];          // per-warp staged e row
    __shared__ float s_warpmin[8];
    __shared__ float rv[256];               // loss reduction only
    __shared__ float s_rsq;
    __shared__ float s_thr;
    __shared__ int s_cnt;
    __shared__ int s_cand[CAND_CAP];
    __shared__ unsigned long long s_best;

    int n = blockIdx.x;
    int tid = threadIdx.x;
    int wid = tid >> 5, lane = tid & 31;
    long ubase = (long)n * NE;
    for (int j = tid; j < NE; j += 256) { u[j] = g_u[ubase + j]; esq_s[j] = g_esq[j]; }
    for (int d = tid; d < EDIM; d += 256) resid[d] = g_zf[(long)n * EDIM + d];
    __syncthreads();

    int idxs[VQ_DEPTH];
#pragma unroll 1
    for (int t = 0; t < VQ_DEPTH; t++) {
        // rsq in replicated reference order (warp 0); warp 1 resets state
        if (wid == 0) {
            float acc = 0.f;
            for (int i = lane; i < EDIM; i += 32)
                acc = __fadd_rn(acc, __fmul_rn(resid[i], resid[i]));
            for (int off = 16; off; off >>= 1)
                acc = __fadd_rn(acc, __shfl_down_sync(0xffffffffu, acc, off));
            if (lane == 0) s_rsq = acc;
        }
        if (tid == 32) { s_cnt = 0; s_best = ~0ULL; }
        __syncthreads();
        float rsq = s_rsq;

        // approx scores, 4 per thread; warp-level min
        float dloc[4];
        float dmin = 3.4e38f;
#pragma unroll
        for (int jj = 0; jj < 4; jj++) {
            int j = tid + jj * 256;
            float q = __fsub_rn(__fadd_rn(rsq, esq_s[j]), u[j]);
            dloc[jj] = q;
            dmin = fminf(dmin, q);
        }
#pragma unroll
        for (int off = 16; off; off >>= 1)
            dmin = fminf(dmin, __shfl_xor_sync(0xffffffffu, dmin, off));
        if (lane == 0) s_warpmin[wid] = dmin;
        __syncthreads();
        if (tid == 0) {
            float m = s_warpmin[0];
#pragma unroll
            for (int w = 1; w < 8; w++) m = fminf(m, s_warpmin[w]);
            s_thr = m + MARGIN;
        }
        __syncthreads();
        float thr = s_thr;

        // gather shortlist
#pragma unroll
        for (int jj = 0; jj < 4; jj++) {
            if (dloc[jj] <= thr) {
                int p = atomicAdd(&s_cnt, 1);
                if (p < CAND_CAP) s_cand[p] = tid + jj * 256;
            }
        }
        __syncthreads();
        int cnt = s_cnt < CAND_CAP ? s_cnt : CAND_CAP;

        int id;
        if (cnt == 1) {
            id = s_cand[0];
        } else {
            // exact refine: candidate c handled by warp c%8; e row staged to smem
            for (int c = wid; c < cnt; c += 8) {
                int j = s_cand[c];
                const float4* ej4 = (const float4*)(emb + (long)j * EDIM);
                float* st = sEj[wid];
#pragma unroll
                for (int q = 0; q < 4; q++) {
                    float4 v = ej4[lane + q * 32];
                    *(float4*)(st + (lane + q * 32) * 4) = v;
                }
                __syncwarp();
                if (lane == 0) {
                    float acc = 0.f;
#pragma unroll 16
                    for (int k = 0; k < EDIM; k++)
                        acc = __fmaf_rn(resid[k], st[k], acc);   // exact seq-k chain
                    float dex = __fsub_rn(__fadd_rn(rsq, esq_s[j]),
                                          __fadd_rn(acc, acc));
                    unsigned long long key =
                        ((unsigned long long)__float_as_uint(dex) << 32) | (unsigned)j;
                    atomicMin(&s_best, key);
                }
                __syncwarp();
            }
            __syncthreads();
            id = (int)(unsigned)(s_best & 0xffffffffULL);
        }
        idxs[t] = id;

        if (t < VQ_DEPTH - 1) {
            const float* g2 = g_G2 + (long)id * NE;
            for (int j = tid; j < NE; j += 256) u[j] = __fsub_rn(u[j], g2[j]);
            const float* er = emb + (long)id * EDIM;
            for (int d = tid; d < EDIM; d += 256) resid[d] = __fsub_rn(resid[d], er[d]);
        }
        __syncthreads();
    }

    if (tid < VQ_DEPTH)
        out[33554433 + tid * N_ROWS + n] = (float)idxs[tid];

    int b = n >> 14, hb = (n >> 7) & 127, wb = n & 127;
    float lp = 0.f;
    for (int d = tid; d < EDIM; d += 256) {
        float zq = 0.f;
#pragma unroll
        for (int t = 0; t < VQ_DEPTH; t++)
            zq = __fadd_rn(zq, emb[(long)idxs[t] * EDIM + d]);
        float zf = g_zf[(long)n * EDIM + d];
        float zq_st = __fadd_rn(zf, __fsub_rn(zq, zf));
        int c = d >> 2, ki = (d >> 1) & 1, kj = d & 1;
        out[(((b << 7) + c) << 16) + (((hb << 1) + ki) << 8) + (wb << 1) + kj] = zq_st;
        float diff = __fsub_rn(zq, zf);
        lp = __fadd_rn(lp, __fmul_rn(diff, diff));
    }
    rv[tid] = lp;
    __syncthreads();
    for (int off = 128; off; off >>= 1) {
        if (tid < off) rv[tid] += rv[tid + off];
        __syncthreads();
    }
    if (tid == 0) g_partial[n] = rv[0];
}

// ---------------------------------------------------------------------------
__global__ void loss_kernel(float* __restrict__ out) {
    __shared__ float sm[256];
    int tid = threadIdx.x;
    float acc = 0.f;
    for (int i = tid; i < N_ROWS; i += 256) acc += g_partial[i];
    sm[tid] = acc;
    __syncthreads();
    for (int off = 128; off; off >>= 1) {
        if (tid < off) sm[tid] += sm[tid + off];
        __syncthreads();
    }
    if (tid == 0) {
        float m = sm[0] / 33554432.0f;
        out[33554432] = __fadd_rn(m, 0.25f * m);
    }
}

// ---------------------------------------------------------------------------
extern "C" void kernel_launch(void* const* d_in, const int* in_sizes, int n_in,
                              void* d_out, int out_size) {
    const float* x   = (const float*)d_in[0];
    const float* emb = (const float*)d_in[1];
    float* out = (float*)d_out;

    unfold_kernel<<<65536, 128>>>(x);
    emb_bf_kernel<<<2048, 256>>>(emb);
    esq_kernel<<<128, 256>>>(emb);
    { dim3 g(8, 8);   gemm_gram_kernel<<<g, 256>>>(emb); }
    { dim3 g(8, 512); gemm_u_mma<<<g, 256>>>(); }
    vq_kernel<<<N_ROWS, 256>>>(emb, out);
    loss_kernel<<<1, 256>>>(out);
}